// round 12
// baseline (speedup 1.0000x reference)
#include <cuda_runtime.h>
#include <mma.h>
#include <cuda_fp16.h>
#include <cstdint>
#include <math.h>

using namespace nvcuda;

// Problem constants
constexpr int Bb = 2, Ss = 2048, Ee = 4096, Hh = 16, Dd = 256, Rr = 64;
constexpr int Mtot = Bb * Ss;                  // 4096
constexpr size_t QK_ELEMS = (size_t)Bb * Hh * Ss * Dd;   // 16777216

// GEMM tiling: CTA 128x128, 8 warps (2x4), warp tile 64x32, fp16, 3-stage pipe
constexpr int BM = 128, BN = 128, BK = 64;     // BK=64 halves = 128 bytes/row
constexpr int NTHREADS = 256;
constexpr int ASTR = BK + 8;                   // 72 halves = 144 B/row
constexpr uint32_t STAGE_A_BYTES = BM * ASTR * 2;        // 18432
constexpr uint32_t STAGE_BYTES = 2 * STAGE_A_BYTES;      // 36864
constexpr int NSTAGE = 3;
constexpr int CSTR = BN + 4;                   // 132
constexpr uint32_t GEMM_SMEM = NSTAGE * STAGE_BYTES;     // 110592 (Cs 67584 fits)
// Fused kernel: stages + rowsum[128] + psum[256]
constexpr uint32_t AUX_OFF = GEMM_SMEM;
constexpr uint32_t FUSED_SMEM = AUX_OFF + 512 + 1024 + 512;   // 112640 (2 CTAs/SM)

// Scratch (fp16 GEMM operands)
__device__ __half g_xnorm[(size_t)Mtot * Ee];
__device__ __half g_wq[(size_t)Ee * Ee];
__device__ __half g_wk[(size_t)Ee * Ee];
__device__ __half g_qr[QK_ELEMS];
__device__ __half g_kr[QK_ELEMS];

__device__ __forceinline__ uint32_t smem_u32(const void* p) {
    uint32_t a;
    asm("{ .reg .u64 t; cvta.to.shared.u64 t, %1; cvt.u32.u64 %0, t; }" : "=r"(a) : "l"(p));
    return a;
}
__device__ __forceinline__ void cp16(uint32_t dst, const void* src) {
    asm volatile("cp.async.cg.shared.global [%0], [%1], 16;" :: "r"(dst), "l"(src));
}
#define CP_COMMIT() asm volatile("cp.async.commit_group;" ::: "memory")
#define CP_WAIT2()  asm volatile("cp.async.wait_group 2;" ::: "memory")

using AccFrag = wmma::fragment<wmma::accumulator, 16, 16, 16, float>;
using AFrag = wmma::fragment<wmma::matrix_a, 16, 16, 16, __half, wmma::row_major>;
using BFrag = wmma::fragment<wmma::matrix_b, 16, 16, 16, __half, wmma::col_major>;

// ---------------------------------------------------------------------------
// LayerNorm -> fp16 g_xnorm
// ---------------------------------------------------------------------------
__global__ void __launch_bounds__(256) ln_kernel(const float* __restrict__ x,
                                                 const float* __restrict__ w,
                                                 const float* __restrict__ b) {
    int row = blockIdx.x;
    int tid = threadIdx.x;
    const float4* xr = reinterpret_cast<const float4*>(x + (size_t)row * Ee);

    float4 v[4];
    float sum = 0.f, ssq = 0.f;
#pragma unroll
    for (int j = 0; j < 4; j++) {
        v[j] = xr[tid + j * 256];
        sum += v[j].x + v[j].y + v[j].z + v[j].w;
        ssq += v[j].x * v[j].x + v[j].y * v[j].y + v[j].z * v[j].z + v[j].w * v[j].w;
    }
    __shared__ float s_sum[8], s_ssq[8];
#pragma unroll
    for (int o = 16; o; o >>= 1) {
        sum += __shfl_xor_sync(~0u, sum, o);
        ssq += __shfl_xor_sync(~0u, ssq, o);
    }
    if ((tid & 31) == 0) { s_sum[tid >> 5] = sum; s_ssq[tid >> 5] = ssq; }
    __syncthreads();
    if (tid < 32) {
        float ts = (tid < 8) ? s_sum[tid] : 0.f;
        float tq = (tid < 8) ? s_ssq[tid] : 0.f;
#pragma unroll
        for (int o = 4; o; o >>= 1) {
            ts += __shfl_xor_sync(~0u, ts, o);
            tq += __shfl_xor_sync(~0u, tq, o);
        }
        if (tid == 0) { s_sum[0] = ts; s_ssq[0] = tq; }
    }
    __syncthreads();
    float mean = s_sum[0] * (1.0f / Ee);
    float var = s_ssq[0] * (1.0f / Ee) - mean * mean;
    float rstd = rsqrtf(var + 1e-5f);

    const float4* wr = reinterpret_cast<const float4*>(w);
    const float4* br = reinterpret_cast<const float4*>(b);
    __half2* outr = reinterpret_cast<__half2*>(g_xnorm + (size_t)row * Ee);
#pragma unroll
    for (int j = 0; j < 4; j++) {
        int c = tid + j * 256;
        float4 wv = wr[c], bv = br[c];
        float o0 = (v[j].x - mean) * rstd * wv.x + bv.x;
        float o1 = (v[j].y - mean) * rstd * wv.y + bv.y;
        float o2 = (v[j].z - mean) * rstd * wv.z + bv.z;
        float o3 = (v[j].w - mean) * rstd * wv.w + bv.w;
        outr[c * 2]     = __floats2half2_rn(o0, o1);
        outr[c * 2 + 1] = __floats2half2_rn(o2, o3);
    }
}

// ---------------------------------------------------------------------------
// Weight conversion fp32 -> fp16
// ---------------------------------------------------------------------------
__global__ void __launch_bounds__(256) wconv_kernel(const float* __restrict__ wq,
                                                    const float* __restrict__ wk) {
    const float* src = blockIdx.y ? wk : wq;
    __half* dst = blockIdx.y ? g_wk : g_wq;
    size_t i = ((size_t)blockIdx.x * 256 + threadIdx.x) * 4;
    float4 v = *reinterpret_cast<const float4*>(src + i);
    __half2* d2 = reinterpret_cast<__half2*>(dst + i);
    d2[0] = __floats2half2_rn(v.x, v.y);
    d2[1] = __floats2half2_rn(v.z, v.w);
}

// ---------------------------------------------------------------------------
// Pipelined fp16 wmma GEMM (NT), CTA 128x128, 8 warps, warp tile 64x32
// ---------------------------------------------------------------------------
__device__ __forceinline__ void load_chunk(uint32_t sb, const char* Ab, const char* Bbp,
                                           size_t ldab, int kc, int buf, int tid) {
    uint32_t stA = sb + buf * STAGE_BYTES;
    uint32_t stB = stA + STAGE_A_BYTES;
    const char* Ap = Ab + (size_t)kc * (BK * 2);
    const char* Bp = Bbp + (size_t)kc * (BK * 2);
#pragma unroll
    for (int l = 0; l < 4; l++) {
        int idx = tid + l * NTHREADS;    // 0..1023
        int r = idx >> 3, cb = (idx & 7) << 4;
        cp16(stA + r * (ASTR * 2) + cb, Ap + (size_t)r * ldab + cb);
        cp16(stB + r * (ASTR * 2) + cb, Bp + (size_t)r * ldab + cb);
    }
}

template <int NCHUNK>
__device__ __forceinline__ void gemm_pipe(const char* Ab, const char* Bbp, size_t ldab,
                                          char* smem, AccFrag acc[4][2]) {
    uint32_t sb = smem_u32(smem);
    int tid = threadIdx.x;
    int warp = tid >> 5;
    int wm = warp & 1;        // 2 along M, 64 rows each
    int wn = warp >> 1;       // 4 along N, 32 cols each

    load_chunk(sb, Ab, Bbp, ldab, 0, 0, tid);
    CP_COMMIT();
    if (NCHUNK > 1) load_chunk(sb, Ab, Bbp, ldab, 1, 1, tid);
    CP_COMMIT();

    for (int k = 0; k < NCHUNK; k++) {
        if (k + 2 < NCHUNK) load_chunk(sb, Ab, Bbp, ldab, k + 2, (k + 2) % NSTAGE, tid);
        CP_COMMIT();
        CP_WAIT2();
        __syncthreads();

        __half* As = reinterpret_cast<__half*>(smem + (k % NSTAGE) * STAGE_BYTES);
        __half* Bs = As + BM * ASTR;
#pragma unroll
        for (int kk = 0; kk < BK; kk += 16) {
            AFrag af[4];
            BFrag bf[2];
#pragma unroll
            for (int i = 0; i < 4; i++)
                wmma::load_matrix_sync(af[i], As + (wm * 64 + i * 16) * ASTR + kk, ASTR);
#pragma unroll
            for (int j = 0; j < 2; j++)
                wmma::load_matrix_sync(bf[j], Bs + (wn * 32 + j * 16) * ASTR + kk, ASTR);
#pragma unroll
            for (int i = 0; i < 4; i++)
#pragma unroll
                for (int j = 0; j < 2; j++)
                    wmma::mma_sync(acc[i][j], af[i], bf[j], acc[i][j]);
        }
        __syncthreads();
    }
}

__device__ __forceinline__ void store_acc(float* Cs, AccFrag acc[4][2]) {
    int warp = threadIdx.x >> 5;
    int wm = warp & 1, wn = warp >> 1;
#pragma unroll
    for (int i = 0; i < 4; i++)
#pragma unroll
        for (int j = 0; j < 2; j++)
            wmma::store_matrix_sync(Cs + (wm * 64 + i * 16) * CSTR + wn * 32 + j * 16,
                                    acc[i][j], CSTR, wmma::mem_row_major);
}

// ---------------------------------------------------------------------------
// Projection GEMM + bias + RoPE; fp32 q/k to d_out, fp16 copies for scores
// ---------------------------------------------------------------------------
__global__ void __launch_bounds__(NTHREADS, 2) proj_cp_kernel(
    const float* __restrict__ bq, const float* __restrict__ bk,
    const float* __restrict__ embed, const int* __restrict__ posids,
    float* __restrict__ qout, float* __restrict__ kout)
{
    extern __shared__ __align__(128) char smem[];
    int z = blockIdx.z;
    const __half* W   = z ? g_wk : g_wq;
    const float* bias = z ? bk : bq;
    float* outp       = z ? kout : qout;
    __half* routp     = z ? g_kr : g_qr;
    const int m0 = blockIdx.x * BM;
    const int n0 = blockIdx.y * BN;

    AccFrag acc[4][2];
#pragma unroll
    for (int i = 0; i < 4; i++)
#pragma unroll
        for (int j = 0; j < 2; j++)
            wmma::fill_fragment(acc[i][j], 0.f);

    gemm_pipe<Ee / BK>(reinterpret_cast<const char*>(g_xnorm + (size_t)m0 * Ee),
                       reinterpret_cast<const char*>(W + (size_t)n0 * Ee),
                       (size_t)Ee * 2, smem, acc);

    float* Cs = reinterpret_cast<float*>(smem);
    store_acc(Cs, acc);
    __syncthreads();

    int tid = threadIdx.x;
#pragma unroll 4
    for (int i = 0; i < 32; i++) {
        int it = tid + i * NTHREADS;     // 0..8191 over 128x64 pairs
        int r = it >> 6;                 // 0..127
        int pc = it & 63;
        int c = pc << 1;
        int m = m0 + r, f = n0 + c;
        float v0 = Cs[r * CSTR + c] + bias[f];
        float v1 = Cs[r * CSTR + c + 1] + bias[f + 1];
        int d = f & 255;
        if (d < Rr) {
            int pos = posids[m];
            int i2 = d >> 1;
            float sn = embed[pos * Rr + i2];
            float co = embed[pos * Rr + 32 + i2];
            float o0 = v0 * co - v1 * sn;
            float o1 = v1 * co + v0 * sn;
            v0 = o0; v1 = o1;
        }
        int b_ = m >> 11, s_ = m & 2047, h_ = f >> 8;
        size_t off = ((size_t)(b_ * Hh + h_) * Ss + s_) * Dd + d;
        *reinterpret_cast<float2*>(outp + off) = make_float2(v0, v1);
        *reinterpret_cast<__half2*>(routp + off) = __floats2half2_rn(v0, v1);
    }
}

// ---------------------------------------------------------------------------
// Fused scores+softmax: one CTA per (q-tile, bh).
// Pass 1: recomputable GEMM over kt<=qt, accumulate rowsum of exp(score/16).
// Pass 2: recompute, write exp(score/16)/rowsum. Then zero masked tiles.
// No-max softmax: |score/16| bounded (<~16), fp32 exp/sum exact enough.
// ---------------------------------------------------------------------------
__global__ void __launch_bounds__(NTHREADS, 2) scores_softmax_kernel(float* __restrict__ attn)
{
    int qt = blockIdx.x;               // 0..15
    int bh = blockIdx.y;               // 0..31
    extern __shared__ __align__(128) char smem[];
    float* rowsum = reinterpret_cast<float*>(smem + AUX_OFF);       // [128]
    float* psum   = rowsum + 128;                                    // [256]

    int m0 = qt * BM;
    const __half* Q  = g_qr + (size_t)bh * Ss * Dd;
    const __half* Kv = g_kr + (size_t)bh * Ss * Dd;
    const char* Ab = reinterpret_cast<const char*>(Q + (size_t)m0 * Dd);
    int tid = threadIdx.x;

    if (tid < 128) rowsum[tid] = 0.f;
    __syncthreads();

    // ---- Pass 1: accumulate per-row sum of exp ----
    for (int kt = 0; kt <= qt; kt++) {
        AccFrag acc[4][2];
#pragma unroll
        for (int i = 0; i < 4; i++)
#pragma unroll
            for (int j = 0; j < 2; j++)
                wmma::fill_fragment(acc[i][j], 0.f);
        gemm_pipe<Dd / BK>(Ab,
                           reinterpret_cast<const char*>(Kv + (size_t)kt * BM * Dd),
                           (size_t)Dd * 2, smem, acc);
        float* Cs = reinterpret_cast<float*>(smem);
        store_acc(Cs, acc);
        __syncthreads();

        int r = tid >> 1, h = tid & 1;
        const float* rowp = Cs + r * CSTR + h * 64;
        // valid columns: kt<qt -> all 64; diagonal tile -> col<=r
        int lim = (kt < qt) ? 64 : (h == 0 ? ((r + 1 < 64) ? r + 1 : 64)
                                           : ((r - 63 > 0) ? r - 63 : 0));
        float local = 0.f;
        for (int c = 0; c < lim; c++)
            local += __expf(rowp[c] * 0.0625f);
        psum[tid] = local;
        __syncthreads();
        if (tid < 128) rowsum[tid] += psum[2 * tid] + psum[2 * tid + 1];
        __syncthreads();
    }
    if (tid < 128) rowsum[tid] = 1.0f / rowsum[tid];
    __syncthreads();

    float* out_base = attn + (size_t)bh * Ss * Ss;

    // ---- Pass 2: recompute and write normalized probabilities ----
    for (int kt = 0; kt <= qt; kt++) {
        AccFrag acc[4][2];
#pragma unroll
        for (int i = 0; i < 4; i++)
#pragma unroll
            for (int j = 0; j < 2; j++)
                wmma::fill_fragment(acc[i][j], 0.f);
        gemm_pipe<Dd / BK>(Ab,
                           reinterpret_cast<const char*>(Kv + (size_t)kt * BM * Dd),
                           (size_t)Dd * 2, smem, acc);
        float* Cs = reinterpret_cast<float*>(smem);
        store_acc(Cs, acc);
        __syncthreads();

        int n0 = kt * BM;
#pragma unroll
        for (int i = 0; i < 16; i++) {
            int it = tid + i * NTHREADS;   // 0..4095 float4s over 128x128
            int r = it >> 5;
            int c4 = (it & 31) << 2;
            int gr = m0 + r;
            float inv = rowsum[r];
            float4 v = *reinterpret_cast<const float4*>(Cs + r * CSTR + c4);
            float4 o;
            o.x = (n0 + c4 + 0 <= gr) ? __expf(v.x * 0.0625f) * inv : 0.f;
            o.y = (n0 + c4 + 1 <= gr) ? __expf(v.y * 0.0625f) * inv : 0.f;
            o.z = (n0 + c4 + 2 <= gr) ? __expf(v.z * 0.0625f) * inv : 0.f;
            o.w = (n0 + c4 + 3 <= gr) ? __expf(v.w * 0.0625f) * inv : 0.f;
            *reinterpret_cast<float4*>(out_base + (size_t)gr * Ss + n0 + c4) = o;
        }
        __syncthreads();
    }

    // ---- Zero fully-masked region (also clears harness poison) ----
    int zn0 = (qt + 1) * BM;
    if (zn0 < Ss) {
        float4 z4 = make_float4(0.f, 0.f, 0.f, 0.f);
        int rowlen4 = (Ss - zn0) >> 2;          // float4s per row
        for (int r = 0; r < BM; r++) {
            float4* rp = reinterpret_cast<float4*>(out_base + (size_t)(m0 + r) * Ss + zn0);
            for (int c = tid; c < rowlen4; c += NTHREADS)
                rp[c] = z4;
        }
    }
}

// ---------------------------------------------------------------------------
extern "C" void kernel_launch(void* const* d_in, const int* in_sizes, int n_in,
                              void* d_out, int out_size) {
    const float* x     = (const float*)d_in[0];
    const float* q_w   = (const float*)d_in[1];
    const float* q_b   = (const float*)d_in[2];
    const float* k_w   = (const float*)d_in[3];
    const float* k_b   = (const float*)d_in[4];
    const float* ln_w  = (const float*)d_in[5];
    const float* ln_b  = (const float*)d_in[6];
    const float* embed = (const float*)d_in[7];
    const int*   pos   = (const int*)d_in[8];

    float* out   = (float*)d_out;
    float* q_out = out;
    float* k_out = out + QK_ELEMS;
    float* attn  = out + 2 * QK_ELEMS;

    cudaFuncSetAttribute(proj_cp_kernel, cudaFuncAttributeMaxDynamicSharedMemorySize, (int)GEMM_SMEM);
    cudaFuncSetAttribute(scores_softmax_kernel, cudaFuncAttributeMaxDynamicSharedMemorySize, (int)FUSED_SMEM);

    ln_kernel<<<Mtot, 256>>>(x, ln_w, ln_b);

    dim3 gw((unsigned)(((size_t)Ee * Ee) / 1024), 2);   // 16384 x 2
    wconv_kernel<<<gw, 256>>>(q_w, k_w);

    dim3 gp(Mtot / BM, Ee / BN, 2);          // (32, 32, 2), x over M
    proj_cp_kernel<<<gp, NTHREADS, GEMM_SMEM>>>(q_b, k_b, embed, pos, q_out, k_out);

    dim3 gf(Ss / BM, Bb * Hh);               // (16, 32)
    scores_softmax_kernel<<<gf, NTHREADS, FUSED_SMEM>>>(attn);
}

// round 13
// speedup vs baseline: 1.0945x; 1.0945x over previous
#include <cuda_runtime.h>
#include <mma.h>
#include <cuda_fp16.h>
#include <cstdint>
#include <math.h>

using namespace nvcuda;

// Problem constants
constexpr int Bb = 2, Ss = 2048, Ee = 4096, Hh = 16, Dd = 256, Rr = 64;
constexpr int Mtot = Bb * Ss;                  // 4096
constexpr size_t QK_ELEMS = (size_t)Bb * Hh * Ss * Dd;   // 16777216

// Common tiling
constexpr int BM = 128, BN = 128, BK = 64;     // BK=64 halves = 128 bytes/row
constexpr int NTHREADS = 256;
constexpr int ASTR = BK + 8;                   // 72 halves = 144 B/row
constexpr int CSTR = BN + 4;                   // 132

// Scores: CTA 128x128, 3-stage, 2 CTAs/SM (R11 winner)
constexpr uint32_t STAGE_A_BYTES = BM * ASTR * 2;        // 18432
constexpr uint32_t STAGE_BYTES = 2 * STAGE_A_BYTES;      // 36864
constexpr int NSTAGE = 3;
constexpr uint32_t GEMM_SMEM = NSTAGE * STAGE_BYTES;     // 110592

// Dual proj: per stage [A | Bq | Bk], 4 stages, 1 CTA/SM
constexpr uint32_t PD_A = BM * ASTR * 2;                 // 18432
constexpr uint32_t PD_STAGE = 3 * PD_A;                  // 55296
constexpr int PD_NSTAGE = 4;
constexpr uint32_t PROJ_SMEM = PD_NSTAGE * PD_STAGE;     // 221184 (Cs 67584 fits)

// Scratch (fp16 GEMM operands)
__device__ __half g_xnorm[(size_t)Mtot * Ee];
__device__ __half g_wq[(size_t)Ee * Ee];
__device__ __half g_wk[(size_t)Ee * Ee];
__device__ __half g_qr[QK_ELEMS];
__device__ __half g_kr[QK_ELEMS];

__device__ __forceinline__ uint32_t smem_u32(const void* p) {
    uint32_t a;
    asm("{ .reg .u64 t; cvta.to.shared.u64 t, %1; cvt.u32.u64 %0, t; }" : "=r"(a) : "l"(p));
    return a;
}
__device__ __forceinline__ void cp16(uint32_t dst, const void* src) {
    asm volatile("cp.async.cg.shared.global [%0], [%1], 16;" :: "r"(dst), "l"(src));
}
#define CP_COMMIT() asm volatile("cp.async.commit_group;" ::: "memory")
#define CP_WAIT1()  asm volatile("cp.async.wait_group 1;" ::: "memory")
#define CP_WAIT2()  asm volatile("cp.async.wait_group 2;" ::: "memory")

using AccFrag = wmma::fragment<wmma::accumulator, 16, 16, 16, float>;
using AFrag = wmma::fragment<wmma::matrix_a, 16, 16, 16, __half, wmma::row_major>;
using BFrag = wmma::fragment<wmma::matrix_b, 16, 16, 16, __half, wmma::col_major>;

// ---------------------------------------------------------------------------
// LayerNorm -> fp16 g_xnorm
// ---------------------------------------------------------------------------
__global__ void __launch_bounds__(256) ln_kernel(const float* __restrict__ x,
                                                 const float* __restrict__ w,
                                                 const float* __restrict__ b) {
    int row = blockIdx.x;
    int tid = threadIdx.x;
    const float4* xr = reinterpret_cast<const float4*>(x + (size_t)row * Ee);

    float4 v[4];
    float sum = 0.f, ssq = 0.f;
#pragma unroll
    for (int j = 0; j < 4; j++) {
        v[j] = xr[tid + j * 256];
        sum += v[j].x + v[j].y + v[j].z + v[j].w;
        ssq += v[j].x * v[j].x + v[j].y * v[j].y + v[j].z * v[j].z + v[j].w * v[j].w;
    }
    __shared__ float s_sum[8], s_ssq[8];
#pragma unroll
    for (int o = 16; o; o >>= 1) {
        sum += __shfl_xor_sync(~0u, sum, o);
        ssq += __shfl_xor_sync(~0u, ssq, o);
    }
    if ((tid & 31) == 0) { s_sum[tid >> 5] = sum; s_ssq[tid >> 5] = ssq; }
    __syncthreads();
    if (tid < 32) {
        float ts = (tid < 8) ? s_sum[tid] : 0.f;
        float tq = (tid < 8) ? s_ssq[tid] : 0.f;
#pragma unroll
        for (int o = 4; o; o >>= 1) {
            ts += __shfl_xor_sync(~0u, ts, o);
            tq += __shfl_xor_sync(~0u, tq, o);
        }
        if (tid == 0) { s_sum[0] = ts; s_ssq[0] = tq; }
    }
    __syncthreads();
    float mean = s_sum[0] * (1.0f / Ee);
    float var = s_ssq[0] * (1.0f / Ee) - mean * mean;
    float rstd = rsqrtf(var + 1e-5f);

    const float4* wr = reinterpret_cast<const float4*>(w);
    const float4* br = reinterpret_cast<const float4*>(b);
    __half2* outr = reinterpret_cast<__half2*>(g_xnorm + (size_t)row * Ee);
#pragma unroll
    for (int j = 0; j < 4; j++) {
        int c = tid + j * 256;
        float4 wv = wr[c], bv = br[c];
        float o0 = (v[j].x - mean) * rstd * wv.x + bv.x;
        float o1 = (v[j].y - mean) * rstd * wv.y + bv.y;
        float o2 = (v[j].z - mean) * rstd * wv.z + bv.z;
        float o3 = (v[j].w - mean) * rstd * wv.w + bv.w;
        outr[c * 2]     = __floats2half2_rn(o0, o1);
        outr[c * 2 + 1] = __floats2half2_rn(o2, o3);
    }
}

// ---------------------------------------------------------------------------
// Weight conversion fp32 -> fp16
// ---------------------------------------------------------------------------
__global__ void __launch_bounds__(256) wconv_kernel(const float* __restrict__ wq,
                                                    const float* __restrict__ wk) {
    const float* src = blockIdx.y ? wk : wq;
    __half* dst = blockIdx.y ? g_wk : g_wq;
    size_t i = ((size_t)blockIdx.x * 256 + threadIdx.x) * 4;
    float4 v = *reinterpret_cast<const float4*>(src + i);
    __half2* d2 = reinterpret_cast<__half2*>(dst + i);
    d2[0] = __floats2half2_rn(v.x, v.y);
    d2[1] = __floats2half2_rn(v.z, v.w);
}

// ---------------------------------------------------------------------------
// Dual projection GEMM: one CTA computes Q and K 128x128 tiles, sharing A.
// 4-stage cp.async pipeline, ONE __syncthreads per chunk.
// ---------------------------------------------------------------------------
__device__ __forceinline__ void pd_load_chunk(uint32_t sb,
                                              const char* Ab, const char* Bq, const char* Bk,
                                              int kc, int buf, int tid) {
    uint32_t stA = sb + buf * PD_STAGE;
    uint32_t stBq = stA + PD_A;
    uint32_t stBk = stBq + PD_A;
    size_t koff = (size_t)kc * (BK * 2);
#pragma unroll
    for (int l = 0; l < 4; l++) {
        int idx = tid + l * NTHREADS;    // 0..1023
        int r = idx >> 3, cb = (idx & 7) << 4;
        size_t goff = (size_t)r * (Ee * 2) + koff + cb;
        uint32_t soff = r * (ASTR * 2) + cb;
        cp16(stA + soff, Ab + goff);
        cp16(stBq + soff, Bq + goff);
        cp16(stBk + soff, Bk + goff);
    }
}

__device__ __forceinline__ void proj_epilogue(float* Cs, AccFrag acc[4][2],
                                              const float* __restrict__ bias,
                                              const float* __restrict__ embed,
                                              const int* __restrict__ posids,
                                              float* __restrict__ outp,
                                              __half* __restrict__ routp,
                                              int m0, int n0, int tid) {
    int warp = tid >> 5;
    int wm = warp & 1, wn = warp >> 1;
#pragma unroll
    for (int i = 0; i < 4; i++)
#pragma unroll
        for (int j = 0; j < 2; j++)
            wmma::store_matrix_sync(Cs + (wm * 64 + i * 16) * CSTR + wn * 32 + j * 16,
                                    acc[i][j], CSTR, wmma::mem_row_major);
    __syncthreads();
#pragma unroll 4
    for (int i = 0; i < 32; i++) {
        int it = tid + i * NTHREADS;     // 0..8191 over 128x64 pairs
        int r = it >> 6;                 // 0..127
        int pc = it & 63;
        int c = pc << 1;
        int m = m0 + r, f = n0 + c;
        float v0 = Cs[r * CSTR + c] + bias[f];
        float v1 = Cs[r * CSTR + c + 1] + bias[f + 1];
        int d = f & 255;
        if (d < Rr) {
            int pos = posids[m];
            int i2 = d >> 1;
            float sn = embed[pos * Rr + i2];
            float co = embed[pos * Rr + 32 + i2];
            float o0 = v0 * co - v1 * sn;
            float o1 = v1 * co + v0 * sn;
            v0 = o0; v1 = o1;
        }
        int b_ = m >> 11, s_ = m & 2047, h_ = f >> 8;
        size_t off = ((size_t)(b_ * Hh + h_) * Ss + s_) * Dd + d;
        *reinterpret_cast<float2*>(outp + off) = make_float2(v0, v1);
        *reinterpret_cast<__half2*>(routp + off) = __floats2half2_rn(v0, v1);
    }
    __syncthreads();
}

__global__ void __launch_bounds__(NTHREADS, 1) proj_dual_kernel(
    const float* __restrict__ bq, const float* __restrict__ bk,
    const float* __restrict__ embed, const int* __restrict__ posids,
    float* __restrict__ qout, float* __restrict__ kout)
{
    extern __shared__ __align__(128) char smem[];
    uint32_t sb = smem_u32(smem);
    const int m0 = blockIdx.x * BM;   // x fastest: consecutive CTAs share weight panels
    const int n0 = blockIdx.y * BN;
    int tid = threadIdx.x;
    int warp = tid >> 5;
    int wm = warp & 1;        // 2 along M, 64 rows each
    int wn = warp >> 1;       // 4 along N, 32 cols each

    const char* Ab = reinterpret_cast<const char*>(g_xnorm + (size_t)m0 * Ee);
    const char* Bq = reinterpret_cast<const char*>(g_wq + (size_t)n0 * Ee);
    const char* Bk = reinterpret_cast<const char*>(g_wk + (size_t)n0 * Ee);

    AccFrag accq[4][2], acck[4][2];
#pragma unroll
    for (int i = 0; i < 4; i++)
#pragma unroll
        for (int j = 0; j < 2; j++) {
            wmma::fill_fragment(accq[i][j], 0.f);
            wmma::fill_fragment(acck[i][j], 0.f);
        }

    pd_load_chunk(sb, Ab, Bq, Bk, 0, 0, tid);
    CP_COMMIT();
    pd_load_chunk(sb, Ab, Bq, Bk, 1, 1, tid);
    CP_COMMIT();

    constexpr int NCHUNK = Ee / BK;   // 64
    for (int k = 0; k < NCHUNK; k++) {
        CP_WAIT1();                   // chunk k resident for this thread
        __syncthreads();              // ... and for all threads
        if (k + 2 < NCHUNK)
            pd_load_chunk(sb, Ab, Bq, Bk, k + 2, (k + 2) & 3, tid);
        CP_COMMIT();

        __half* As = reinterpret_cast<__half*>(smem + (k & 3) * PD_STAGE);
        __half* Bqs = As + BM * ASTR;
        __half* Bks = Bqs + BM * ASTR;
#pragma unroll
        for (int kk = 0; kk < BK; kk += 16) {
            AFrag af[4];
            BFrag bfq[2], bfk[2];
#pragma unroll
            for (int i = 0; i < 4; i++)
                wmma::load_matrix_sync(af[i], As + (wm * 64 + i * 16) * ASTR + kk, ASTR);
#pragma unroll
            for (int j = 0; j < 2; j++) {
                wmma::load_matrix_sync(bfq[j], Bqs + (wn * 32 + j * 16) * ASTR + kk, ASTR);
                wmma::load_matrix_sync(bfk[j], Bks + (wn * 32 + j * 16) * ASTR + kk, ASTR);
            }
#pragma unroll
            for (int i = 0; i < 4; i++)
#pragma unroll
                for (int j = 0; j < 2; j++) {
                    wmma::mma_sync(accq[i][j], af[i], bfq[j], accq[i][j]);
                    wmma::mma_sync(acck[i][j], af[i], bfk[j], acck[i][j]);
                }
        }
        __syncthreads();   // all consumers done with buf k before producer reuse
    }

    float* Cs = reinterpret_cast<float*>(smem);
    proj_epilogue(Cs, accq, bq, embed, posids, qout, g_qr, m0, n0, tid);
    proj_epilogue(Cs, acck, bk, embed, posids, kout, g_kr, m0, n0, tid);
}

// ---------------------------------------------------------------------------
// Scores GEMM (R11 winner): CTA 128x128, 3-stage, causal tile skip
// ---------------------------------------------------------------------------
__device__ __forceinline__ void load_chunk(uint32_t sb, const char* Ab, const char* Bbp,
                                           size_t ldab, int kc, int buf, int tid) {
    uint32_t stA = sb + buf * STAGE_BYTES;
    uint32_t stB = stA + STAGE_A_BYTES;
    const char* Ap = Ab + (size_t)kc * (BK * 2);
    const char* Bp = Bbp + (size_t)kc * (BK * 2);
#pragma unroll
    for (int l = 0; l < 4; l++) {
        int idx = tid + l * NTHREADS;    // 0..1023
        int r = idx >> 3, cb = (idx & 7) << 4;
        cp16(stA + r * (ASTR * 2) + cb, Ap + (size_t)r * ldab + cb);
        cp16(stB + r * (ASTR * 2) + cb, Bp + (size_t)r * ldab + cb);
    }
}

__global__ void __launch_bounds__(NTHREADS, 2) scores_cp_kernel(float* __restrict__ attn)
{
    int kt = blockIdx.x, qt = blockIdx.y, bh = blockIdx.z;
    if (kt > qt) return;

    extern __shared__ __align__(128) char smem[];
    uint32_t sb = smem_u32(smem);
    int m0 = qt * BM, n0 = kt * BN;
    const char* Ab = reinterpret_cast<const char*>(g_qr + (size_t)bh * Ss * Dd + (size_t)m0 * Dd);
    const char* Bbp = reinterpret_cast<const char*>(g_kr + (size_t)bh * Ss * Dd + (size_t)n0 * Dd);
    int tid = threadIdx.x;
    int warp = tid >> 5;
    int wm = warp & 1;
    int wn = warp >> 1;

    AccFrag acc[4][2];
#pragma unroll
    for (int i = 0; i < 4; i++)
#pragma unroll
        for (int j = 0; j < 2; j++)
            wmma::fill_fragment(acc[i][j], 0.f);

    load_chunk(sb, Ab, Bbp, (size_t)Dd * 2, 0, 0, tid);
    CP_COMMIT();
    load_chunk(sb, Ab, Bbp, (size_t)Dd * 2, 1, 1, tid);
    CP_COMMIT();

    constexpr int NCHUNK = Dd / BK;   // 4
#pragma unroll
    for (int k = 0; k < NCHUNK; k++) {
        if (k + 2 < NCHUNK) load_chunk(sb, Ab, Bbp, (size_t)Dd * 2, k + 2, (k + 2) % NSTAGE, tid);
        CP_COMMIT();
        CP_WAIT2();
        __syncthreads();

        __half* As = reinterpret_cast<__half*>(smem + (k % NSTAGE) * STAGE_BYTES);
        __half* Bs = As + BM * ASTR;
#pragma unroll
        for (int kk = 0; kk < BK; kk += 16) {
            AFrag af[4];
            BFrag bf[2];
#pragma unroll
            for (int i = 0; i < 4; i++)
                wmma::load_matrix_sync(af[i], As + (wm * 64 + i * 16) * ASTR + kk, ASTR);
#pragma unroll
            for (int j = 0; j < 2; j++)
                wmma::load_matrix_sync(bf[j], Bs + (wn * 32 + j * 16) * ASTR + kk, ASTR);
#pragma unroll
            for (int i = 0; i < 4; i++)
#pragma unroll
                for (int j = 0; j < 2; j++)
                    wmma::mma_sync(acc[i][j], af[i], bf[j], acc[i][j]);
        }
        __syncthreads();
    }

    float* Cs = reinterpret_cast<float*>(smem);
#pragma unroll
    for (int i = 0; i < 4; i++)
#pragma unroll
        for (int j = 0; j < 2; j++)
            wmma::store_matrix_sync(Cs + (wm * 64 + i * 16) * CSTR + wn * 32 + j * 16,
                                    acc[i][j], CSTR, wmma::mem_row_major);
    __syncthreads();

    float* out_base = attn + (size_t)bh * Ss * Ss;
#pragma unroll
    for (int i = 0; i < 16; i++) {
        int it = tid + i * NTHREADS;       // 0..4095 float4s over 128x128
        int r = it >> 5;
        int c4 = (it & 31) << 2;
        float4 v = *reinterpret_cast<const float4*>(Cs + r * CSTR + c4);
        v.x *= 0.0625f; v.y *= 0.0625f; v.z *= 0.0625f; v.w *= 0.0625f;
        *reinterpret_cast<float4*>(out_base + (size_t)(m0 + r) * Ss + n0 + c4) = v;
    }
}

// ---------------------------------------------------------------------------
// In-place masked softmax, float4 vectorized (R11 winner)
// ---------------------------------------------------------------------------
__global__ void __launch_bounds__(256) softmax_kernel(float* __restrict__ attn) {
    int row = blockIdx.x;
    int q = row & 2047;
    int nv = q + 1;
    float* rowp = attn + (size_t)row * Ss;
    int tid = threadIdx.x;

    float4 vals[2];
    float mx = -INFINITY;
#pragma unroll
    for (int j = 0; j < 2; j++) {
        int k4 = (tid + j * 256) << 2;
        float4 v;
        if (k4 + 3 < nv) {
            v = *reinterpret_cast<const float4*>(rowp + k4);
        } else {
            v.x = (k4 + 0 < nv) ? rowp[k4 + 0] : -INFINITY;
            v.y = (k4 + 1 < nv) ? rowp[k4 + 1] : -INFINITY;
            v.z = (k4 + 2 < nv) ? rowp[k4 + 2] : -INFINITY;
            v.w = (k4 + 3 < nv) ? rowp[k4 + 3] : -INFINITY;
        }
        vals[j] = v;
        mx = fmaxf(mx, fmaxf(fmaxf(v.x, v.y), fmaxf(v.z, v.w)));
    }
    __shared__ float sh[8];
#pragma unroll
    for (int o = 16; o; o >>= 1) mx = fmaxf(mx, __shfl_xor_sync(~0u, mx, o));
    if ((tid & 31) == 0) sh[tid >> 5] = mx;
    __syncthreads();
    if (tid < 32) {
        float t = (tid < 8) ? sh[tid] : -INFINITY;
#pragma unroll
        for (int o = 4; o; o >>= 1) t = fmaxf(t, __shfl_xor_sync(~0u, t, o));
        if (tid == 0) sh[0] = t;
    }
    __syncthreads();
    float M = sh[0];
    __syncthreads();

    float sum = 0.f;
#pragma unroll
    for (int j = 0; j < 2; j++) {
        float4 v = vals[j];
        v.x = (v.x == -INFINITY) ? 0.f : expf(v.x - M);
        v.y = (v.y == -INFINITY) ? 0.f : expf(v.y - M);
        v.z = (v.z == -INFINITY) ? 0.f : expf(v.z - M);
        v.w = (v.w == -INFINITY) ? 0.f : expf(v.w - M);
        vals[j] = v;
        sum += v.x + v.y + v.z + v.w;
    }
#pragma unroll
    for (int o = 16; o; o >>= 1) sum += __shfl_xor_sync(~0u, sum, o);
    if ((tid & 31) == 0) sh[tid >> 5] = sum;
    __syncthreads();
    if (tid < 32) {
        float t = (tid < 8) ? sh[tid] : 0.f;
#pragma unroll
        for (int o = 4; o; o >>= 1) t += __shfl_xor_sync(~0u, t, o);
        if (tid == 0) sh[0] = t;
    }
    __syncthreads();
    float inv = 1.0f / sh[0];
#pragma unroll
    for (int j = 0; j < 2; j++) {
        int k4 = (tid + j * 256) << 2;
        float4 v = vals[j];
        v.x *= inv; v.y *= inv; v.z *= inv; v.w *= inv;
        *reinterpret_cast<float4*>(rowp + k4) = v;
    }
}

// ---------------------------------------------------------------------------
extern "C" void kernel_launch(void* const* d_in, const int* in_sizes, int n_in,
                              void* d_out, int out_size) {
    const float* x     = (const float*)d_in[0];
    const float* q_w   = (const float*)d_in[1];
    const float* q_b   = (const float*)d_in[2];
    const float* k_w   = (const float*)d_in[3];
    const float* k_b   = (const float*)d_in[4];
    const float* ln_w  = (const float*)d_in[5];
    const float* ln_b  = (const float*)d_in[6];
    const float* embed = (const float*)d_in[7];
    const int*   pos   = (const int*)d_in[8];

    float* out   = (float*)d_out;
    float* q_out = out;
    float* k_out = out + QK_ELEMS;
    float* attn  = out + 2 * QK_ELEMS;

    cudaFuncSetAttribute(proj_dual_kernel, cudaFuncAttributeMaxDynamicSharedMemorySize, (int)PROJ_SMEM);
    cudaFuncSetAttribute(scores_cp_kernel, cudaFuncAttributeMaxDynamicSharedMemorySize, (int)GEMM_SMEM);

    ln_kernel<<<Mtot, 256>>>(x, ln_w, ln_b);

    dim3 gw((unsigned)(((size_t)Ee * Ee) / 1024), 2);   // 16384 x 2
    wconv_kernel<<<gw, 256>>>(q_w, k_w);

    dim3 gp(Mtot / BM, Ee / BN);             // (32, 32), x over M
    proj_dual_kernel<<<gp, NTHREADS, PROJ_SMEM>>>(q_b, k_b, embed, pos, q_out, k_out);

    dim3 g2(Ss / BN, Ss / BM, Bb * Hh);      // (16, 16, 32)
    scores_cp_kernel<<<g2, NTHREADS, GEMM_SMEM>>>(attn);

    softmax_kernel<<<Bb * Hh * Ss, 256>>>(attn);
}

// round 15
// speedup vs baseline: 1.1811x; 1.0791x over previous
#include <cuda_runtime.h>
#include <mma.h>
#include <cuda_fp16.h>
#include <cstdint>
#include <math.h>

using namespace nvcuda;

// Problem constants
constexpr int Bb = 2, Ss = 2048, Ee = 4096, Hh = 16, Dd = 256, Rr = 64;
constexpr int Mtot = Bb * Ss;                  // 4096
constexpr size_t QK_ELEMS = (size_t)Bb * Hh * Ss * Dd;   // 16777216

// GEMM tiling: CTA 128x128, 8 warps (2x4), warp tile 64x32, fp16, 3-stage pipe
constexpr int BM = 128, BN = 128, BK = 64;     // BK=64 halves = 128 bytes/row
constexpr int NTHREADS = 256;
constexpr int ASTR = BK + 8;                   // 72 halves = 144 B/row
constexpr uint32_t STAGE_A_BYTES = BM * ASTR * 2;        // 18432
constexpr uint32_t STAGE_BYTES = 2 * STAGE_A_BYTES;      // 36864
constexpr int NSTAGE = 3;
constexpr int CSTR = BN + 4;                   // 132
constexpr uint32_t GEMM_SMEM = NSTAGE * STAGE_BYTES;     // 110592 (2 CTAs/SM)

// Scratch (fp16 GEMM operands)
__device__ __half g_xnorm[(size_t)Mtot * Ee];
__device__ __half g_wq[(size_t)Ee * Ee];
__device__ __half g_wk[(size_t)Ee * Ee];
__device__ __half g_qr[QK_ELEMS];
__device__ __half g_kr[QK_ELEMS];

__device__ __forceinline__ uint32_t smem_u32(const void* p) {
    uint32_t a;
    asm("{ .reg .u64 t; cvta.to.shared.u64 t, %1; cvt.u32.u64 %0, t; }" : "=r"(a) : "l"(p));
    return a;
}
__device__ __forceinline__ void cp16(uint32_t dst, const void* src) {
    asm volatile("cp.async.cg.shared.global [%0], [%1], 16;" :: "r"(dst), "l"(src));
}
__device__ __forceinline__ void stcs2(float* p, float2 v) {
    asm volatile("st.global.cs.v2.f32 [%0], {%1, %2};" :: "l"(p), "f"(v.x), "f"(v.y) : "memory");
}
__device__ __forceinline__ void stcs4(float* p, float4 v) {
    asm volatile("st.global.cs.v4.f32 [%0], {%1, %2, %3, %4};"
                 :: "l"(p), "f"(v.x), "f"(v.y), "f"(v.z), "f"(v.w) : "memory");
}
#define CP_COMMIT() asm volatile("cp.async.commit_group;" ::: "memory")
#define CP_WAIT2()  asm volatile("cp.async.wait_group 2;" ::: "memory")

using AccFrag = wmma::fragment<wmma::accumulator, 16, 16, 16, float>;
using AFrag = wmma::fragment<wmma::matrix_a, 16, 16, 16, __half, wmma::row_major>;
using BFrag = wmma::fragment<wmma::matrix_b, 16, 16, 16, __half, wmma::col_major>;

// ---------------------------------------------------------------------------
// LayerNorm -> fp16 g_xnorm
// ---------------------------------------------------------------------------
__global__ void __launch_bounds__(256) ln_kernel(const float* __restrict__ x,
                                                 const float* __restrict__ w,
                                                 const float* __restrict__ b) {
    int row = blockIdx.x;
    int tid = threadIdx.x;
    const float4* xr = reinterpret_cast<const float4*>(x + (size_t)row * Ee);

    float4 v[4];
    float sum = 0.f, ssq = 0.f;
#pragma unroll
    for (int j = 0; j < 4; j++) {
        v[j] = xr[tid + j * 256];
        sum += v[j].x + v[j].y + v[j].z + v[j].w;
        ssq += v[j].x * v[j].x + v[j].y * v[j].y + v[j].z * v[j].z + v[j].w * v[j].w;
    }
    __shared__ float s_sum[8], s_ssq[8];
#pragma unroll
    for (int o = 16; o; o >>= 1) {
        sum += __shfl_xor_sync(~0u, sum, o);
        ssq += __shfl_xor_sync(~0u, ssq, o);
    }
    if ((tid & 31) == 0) { s_sum[tid >> 5] = sum; s_ssq[tid >> 5] = ssq; }
    __syncthreads();
    if (tid < 32) {
        float ts = (tid < 8) ? s_sum[tid] : 0.f;
        float tq = (tid < 8) ? s_ssq[tid] : 0.f;
#pragma unroll
        for (int o = 4; o; o >>= 1) {
            ts += __shfl_xor_sync(~0u, ts, o);
            tq += __shfl_xor_sync(~0u, tq, o);
        }
        if (tid == 0) { s_sum[0] = ts; s_ssq[0] = tq; }
    }
    __syncthreads();
    float mean = s_sum[0] * (1.0f / Ee);
    float var = s_ssq[0] * (1.0f / Ee) - mean * mean;
    float rstd = rsqrtf(var + 1e-5f);

    const float4* wr = reinterpret_cast<const float4*>(w);
    const float4* br = reinterpret_cast<const float4*>(b);
    __half2* outr = reinterpret_cast<__half2*>(g_xnorm + (size_t)row * Ee);
#pragma unroll
    for (int j = 0; j < 4; j++) {
        int c = tid + j * 256;
        float4 wv = wr[c], bv = br[c];
        float o0 = (v[j].x - mean) * rstd * wv.x + bv.x;
        float o1 = (v[j].y - mean) * rstd * wv.y + bv.y;
        float o2 = (v[j].z - mean) * rstd * wv.z + bv.z;
        float o3 = (v[j].w - mean) * rstd * wv.w + bv.w;
        outr[c * 2]     = __floats2half2_rn(o0, o1);
        outr[c * 2 + 1] = __floats2half2_rn(o2, o3);
    }
}

// ---------------------------------------------------------------------------
// Weight conversion fp32 -> fp16
// ---------------------------------------------------------------------------
__global__ void __launch_bounds__(256) wconv_kernel(const float* __restrict__ wq,
                                                    const float* __restrict__ wk) {
    const float* src = blockIdx.y ? wk : wq;
    __half* dst = blockIdx.y ? g_wk : g_wq;
    size_t i = ((size_t)blockIdx.x * 256 + threadIdx.x) * 4;
    float4 v = *reinterpret_cast<const float4*>(src + i);
    __half2* d2 = reinterpret_cast<__half2*>(dst + i);
    d2[0] = __floats2half2_rn(v.x, v.y);
    d2[1] = __floats2half2_rn(v.z, v.w);
}

// ---------------------------------------------------------------------------
// Pipelined fp16 wmma GEMM (NT), CTA 128x128, 8 warps, warp tile 64x32
// ---------------------------------------------------------------------------
__device__ __forceinline__ void load_chunk(uint32_t sb, const char* Ab, const char* Bbp,
                                           size_t ldab, int kc, int buf, int tid) {
    uint32_t stA = sb + buf * STAGE_BYTES;
    uint32_t stB = stA + STAGE_A_BYTES;
    const char* Ap = Ab + (size_t)kc * (BK * 2);
    const char* Bp = Bbp + (size_t)kc * (BK * 2);
#pragma unroll
    for (int l = 0; l < 4; l++) {
        int idx = tid + l * NTHREADS;    // 0..1023
        int r = idx >> 3, cb = (idx & 7) << 4;
        cp16(stA + r * (ASTR * 2) + cb, Ap + (size_t)r * ldab + cb);
        cp16(stB + r * (ASTR * 2) + cb, Bp + (size_t)r * ldab + cb);
    }
}

template <int NCHUNK>
__device__ __forceinline__ void gemm_pipe(const char* Ab, const char* Bbp, size_t ldab,
                                          char* smem, AccFrag acc[4][2]) {
    uint32_t sb = smem_u32(smem);
    int tid = threadIdx.x;
    int warp = tid >> 5;
    int wm = warp & 1;        // 2 along M, 64 rows each
    int wn = warp >> 1;       // 4 along N, 32 cols each

    load_chunk(sb, Ab, Bbp, ldab, 0, 0, tid);
    CP_COMMIT();
    if (NCHUNK > 1) load_chunk(sb, Ab, Bbp, ldab, 1, 1, tid);
    CP_COMMIT();

    for (int k = 0; k < NCHUNK; k++) {
        if (k + 2 < NCHUNK) load_chunk(sb, Ab, Bbp, ldab, k + 2, (k + 2) % NSTAGE, tid);
        CP_COMMIT();
        CP_WAIT2();
        __syncthreads();

        __half* As = reinterpret_cast<__half*>(smem + (k % NSTAGE) * STAGE_BYTES);
        __half* Bs = As + BM * ASTR;
#pragma unroll
        for (int kk = 0; kk < BK; kk += 16) {
            AFrag af[4];
            BFrag bf[2];
#pragma unroll
            for (int i = 0; i < 4; i++)
                wmma::load_matrix_sync(af[i], As + (wm * 64 + i * 16) * ASTR + kk, ASTR);
#pragma unroll
            for (int j = 0; j < 2; j++)
                wmma::load_matrix_sync(bf[j], Bs + (wn * 32 + j * 16) * ASTR + kk, ASTR);
#pragma unroll
            for (int i = 0; i < 4; i++)
#pragma unroll
                for (int j = 0; j < 2; j++)
                    wmma::mma_sync(acc[i][j], af[i], bf[j], acc[i][j]);
        }
        __syncthreads();
    }
}

__device__ __forceinline__ void store_acc(float* Cs, AccFrag acc[4][2]) {
    int warp = threadIdx.x >> 5;
    int wm = warp & 1, wn = warp >> 1;
#pragma unroll
    for (int i = 0; i < 4; i++)
#pragma unroll
        for (int j = 0; j < 2; j++)
            wmma::store_matrix_sync(Cs + (wm * 64 + i * 16) * CSTR + wn * 32 + j * 16,
                                    acc[i][j], CSTR, wmma::mem_row_major);
}

// ---------------------------------------------------------------------------
// Projection GEMM + bias + RoPE; fp32 q/k to d_out (streaming), fp16 copies
// ---------------------------------------------------------------------------
__global__ void __launch_bounds__(NTHREADS, 2) proj_cp_kernel(
    const float* __restrict__ bq, const float* __restrict__ bk,
    const float* __restrict__ embed, const int* __restrict__ posids,
    float* __restrict__ qout, float* __restrict__ kout)
{
    extern __shared__ __align__(128) char smem[];
    int z = blockIdx.z;
    const __half* W   = z ? g_wk : g_wq;
    const float* bias = z ? bk : bq;
    float* outp       = z ? kout : qout;
    __half* routp     = z ? g_kr : g_qr;
    const int m0 = blockIdx.x * BM;   // x fastest: consecutive CTAs share the weight panel
    const int n0 = blockIdx.y * BN;

    AccFrag acc[4][2];
#pragma unroll
    for (int i = 0; i < 4; i++)
#pragma unroll
        for (int j = 0; j < 2; j++)
            wmma::fill_fragment(acc[i][j], 0.f);

    gemm_pipe<Ee / BK>(reinterpret_cast<const char*>(g_xnorm + (size_t)m0 * Ee),
                       reinterpret_cast<const char*>(W + (size_t)n0 * Ee),
                       (size_t)Ee * 2, smem, acc);

    float* Cs = reinterpret_cast<float*>(smem);
    store_acc(Cs, acc);
    __syncthreads();

    int tid = threadIdx.x;
#pragma unroll 4
    for (int i = 0; i < 32; i++) {
        int it = tid + i * NTHREADS;     // 0..8191 over 128x64 pairs
        int r = it >> 6;                 // 0..127
        int pc = it & 63;
        int c = pc << 1;
        int m = m0 + r, f = n0 + c;
        float v0 = Cs[r * CSTR + c] + bias[f];
        float v1 = Cs[r * CSTR + c + 1] + bias[f + 1];
        int d = f & 255;
        if (d < Rr) {
            int pos = posids[m];
            int i2 = d >> 1;
            float sn = embed[pos * Rr + i2];
            float co = embed[pos * Rr + 32 + i2];
            float o0 = v0 * co - v1 * sn;
            float o1 = v1 * co + v0 * sn;
            v0 = o0; v1 = o1;
        }
        int b_ = m >> 11, s_ = m & 2047, h_ = f >> 8;
        size_t off = ((size_t)(b_ * Hh + h_) * Ss + s_) * Dd + d;
        stcs2(outp + off, make_float2(v0, v1));   // streaming: never re-read
        *reinterpret_cast<__half2*>(routp + off) = __floats2half2_rn(v0, v1);
    }
}

// ---------------------------------------------------------------------------
// Scores GEMM: scores = Qh.Kh^T / 16, causal tile skip
// ---------------------------------------------------------------------------
__global__ void __launch_bounds__(NTHREADS, 2) scores_cp_kernel(float* __restrict__ attn)
{
    int kt = blockIdx.x, qt = blockIdx.y, bh = blockIdx.z;
    if (kt > qt) return;

    extern __shared__ __align__(128) char smem[];
    int m0 = qt * BM, n0 = kt * BN;
    const __half* Q = g_qr + (size_t)bh * Ss * Dd;
    const __half* Kv = g_kr + (size_t)bh * Ss * Dd;

    AccFrag acc[4][2];
#pragma unroll
    for (int i = 0; i < 4; i++)
#pragma unroll
        for (int j = 0; j < 2; j++)
            wmma::fill_fragment(acc[i][j], 0.f);

    gemm_pipe<Dd / BK>(reinterpret_cast<const char*>(Q + (size_t)m0 * Dd),
                       reinterpret_cast<const char*>(Kv + (size_t)n0 * Dd),
                       (size_t)Dd * 2, smem, acc);

    float* Cs = reinterpret_cast<float*>(smem);
    store_acc(Cs, acc);
    __syncthreads();

    float* out_base = attn + (size_t)bh * Ss * Ss;
#pragma unroll
    for (int i = 0; i < 16; i++) {
        int it = threadIdx.x + i * NTHREADS;   // 0..4095 float4s over 128x128
        int r = it >> 5;
        int c4 = (it & 31) << 2;
        float4 v = *reinterpret_cast<const float4*>(Cs + r * CSTR + c4);
        v.x *= 0.0625f; v.y *= 0.0625f; v.z *= 0.0625f; v.w *= 0.0625f;
        *reinterpret_cast<float4*>(out_base + (size_t)(m0 + r) * Ss + n0 + c4) = v;
    }
}

// ---------------------------------------------------------------------------
// In-place masked softmax, float4 vectorized; final writes streaming
// ---------------------------------------------------------------------------
__global__ void __launch_bounds__(256) softmax_kernel(float* __restrict__ attn) {
    int row = blockIdx.x;
    int q = row & 2047;
    int nv = q + 1;
    float* rowp = attn + (size_t)row * Ss;
    int tid = threadIdx.x;

    float4 vals[2];
    float mx = -INFINITY;
#pragma unroll
    for (int j = 0; j < 2; j++) {
        int k4 = (tid + j * 256) << 2;
        float4 v;
        if (k4 + 3 < nv) {
            v = *reinterpret_cast<const float4*>(rowp + k4);
        } else {
            v.x = (k4 + 0 < nv) ? rowp[k4 + 0] : -INFINITY;
            v.y = (k4 + 1 < nv) ? rowp[k4 + 1] : -INFINITY;
            v.z = (k4 + 2 < nv) ? rowp[k4 + 2] : -INFINITY;
            v.w = (k4 + 3 < nv) ? rowp[k4 + 3] : -INFINITY;
        }
        vals[j] = v;
        mx = fmaxf(mx, fmaxf(fmaxf(v.x, v.y), fmaxf(v.z, v.w)));
    }
    __shared__ float sh[8];
#pragma unroll
    for (int o = 16; o; o >>= 1) mx = fmaxf(mx, __shfl_xor_sync(~0u, mx, o));
    if ((tid & 31) == 0) sh[tid >> 5] = mx;
    __syncthreads();
    if (tid < 32) {
        float t = (tid < 8) ? sh[tid] : -INFINITY;
#pragma unroll
        for (int o = 4; o; o >>= 1) t = fmaxf(t, __shfl_xor_sync(~0u, t, o));
        if (tid == 0) sh[0] = t;
    }
    __syncthreads();
    float M = sh[0];
    __syncthreads();

    float sum = 0.f;
#pragma unroll
    for (int j = 0; j < 2; j++) {
        float4 v = vals[j];
        v.x = (v.x == -INFINITY) ? 0.f : __expf(v.x - M);
        v.y = (v.y == -INFINITY) ? 0.f : __expf(v.y - M);
        v.z = (v.z == -INFINITY) ? 0.f : __expf(v.z - M);
        v.w = (v.w == -INFINITY) ? 0.f : __expf(v.w - M);
        vals[j] = v;
        sum += v.x + v.y + v.z + v.w;
    }
#pragma unroll
    for (int o = 16; o; o >>= 1) sum += __shfl_xor_sync(~0u, sum, o);
    if ((tid & 31) == 0) sh[tid >> 5] = sum;
    __syncthreads();
    if (tid < 32) {
        float t = (tid < 8) ? sh[tid] : 0.f;
#pragma unroll
        for (int o = 4; o; o >>= 1) t += __shfl_xor_sync(~0u, t, o);
        if (tid == 0) sh[0] = t;
    }
    __syncthreads();
    float inv = 1.0f / sh[0];
#pragma unroll
    for (int j = 0; j < 2; j++) {
        int k4 = (tid + j * 256) << 2;
        float4 v = vals[j];
        v.x *= inv; v.y *= inv; v.z *= inv; v.w *= inv;
        stcs4(rowp + k4, v);            // streaming: never re-read
    }
}

// ---------------------------------------------------------------------------
extern "C" void kernel_launch(void* const* d_in, const int* in_sizes, int n_in,
                              void* d_out, int out_size) {
    const float* x     = (const float*)d_in[0];
    const float* q_w   = (const float*)d_in[1];
    const float* q_b   = (const float*)d_in[2];
    const float* k_w   = (const float*)d_in[3];
    const float* k_b   = (const float*)d_in[4];
    const float* ln_w  = (const float*)d_in[5];
    const float* ln_b  = (const float*)d_in[6];
    const float* embed = (const float*)d_in[7];
    const int*   pos   = (const int*)d_in[8];

    float* out   = (float*)d_out;
    float* q_out = out;
    float* k_out = out + QK_ELEMS;
    float* attn  = out + 2 * QK_ELEMS;

    cudaFuncSetAttribute(proj_cp_kernel, cudaFuncAttributeMaxDynamicSharedMemorySize, (int)GEMM_SMEM);
    cudaFuncSetAttribute(scores_cp_kernel, cudaFuncAttributeMaxDynamicSharedMemorySize, (int)GEMM_SMEM);

    ln_kernel<<<Mtot, 256>>>(x, ln_w, ln_b);

    dim3 gw((unsigned)(((size_t)Ee * Ee) / 1024), 2);   // 16384 x 2
    wconv_kernel<<<gw, 256>>>(q_w, k_w);

    dim3 gp(Mtot / BM, Ee / BN, 2);          // (32, 32, 2), x over M
    proj_cp_kernel<<<gp, NTHREADS, GEMM_SMEM>>>(q_b, k_b, embed, pos, q_out, k_out);

    dim3 g2(Ss / BN, Ss / BM, Bb * Hh);      // (16, 16, 32)
    scores_cp_kernel<<<g2, NTHREADS, GEMM_SMEM>>>(attn);

    softmax_kernel<<<Bb * Hh * Ss, 256>>>(attn);
}

// round 16
// speedup vs baseline: 1.1895x; 1.0071x over previous
#include <cuda_runtime.h>
#include <mma.h>
#include <cuda_fp16.h>
#include <cstdint>
#include <math.h>

using namespace nvcuda;

// Problem constants
constexpr int Bb = 2, Ss = 2048, Ee = 4096, Hh = 16, Dd = 256, Rr = 64;
constexpr int Mtot = Bb * Ss;                  // 4096
constexpr size_t QK_ELEMS = (size_t)Bb * Hh * Ss * Dd;   // 16777216

// GEMM tiling: CTA 128x128, 8 warps (2x4), warp tile 64x32, fp16, 3-stage pipe
constexpr int BM = 128, BN = 128, BK = 64;     // BK=64 halves = 128 bytes/row
constexpr int NTHREADS = 256;
constexpr int ASTR = BK + 8;                   // 72 halves = 144 B/row
constexpr uint32_t STAGE_A_BYTES = BM * ASTR * 2;        // 18432
constexpr uint32_t STAGE_BYTES = 2 * STAGE_A_BYTES;      // 36864
constexpr int NSTAGE = 3;
constexpr int CSTR = BN + 4;                   // 132
constexpr uint32_t GEMM_SMEM = NSTAGE * STAGE_BYTES;     // 110592 (2 CTAs/SM)

// Scratch (fp16 GEMM operands)
__device__ __half g_xnorm[(size_t)Mtot * Ee];
__device__ __half g_wq[(size_t)Ee * Ee];
__device__ __half g_wk[(size_t)Ee * Ee];
__device__ __half g_qr[QK_ELEMS];
__device__ __half g_kr[QK_ELEMS];

__device__ __forceinline__ uint32_t smem_u32(const void* p) {
    uint32_t a;
    asm("{ .reg .u64 t; cvta.to.shared.u64 t, %1; cvt.u32.u64 %0, t; }" : "=r"(a) : "l"(p));
    return a;
}
__device__ __forceinline__ void cp16(uint32_t dst, const void* src) {
    asm volatile("cp.async.cg.shared.global [%0], [%1], 16;" :: "r"(dst), "l"(src));
}
__device__ __forceinline__ void stcs2(float* p, float2 v) {
    asm volatile("st.global.cs.v2.f32 [%0], {%1, %2};" :: "l"(p), "f"(v.x), "f"(v.y) : "memory");
}
__device__ __forceinline__ void stcs4(float* p, float4 v) {
    asm volatile("st.global.cs.v4.f32 [%0], {%1, %2, %3, %4};"
                 :: "l"(p), "f"(v.x), "f"(v.y), "f"(v.z), "f"(v.w) : "memory");
}
#define CP_COMMIT() asm volatile("cp.async.commit_group;" ::: "memory")
#define CP_WAIT1()  asm volatile("cp.async.wait_group 1;" ::: "memory")

using AccFrag = wmma::fragment<wmma::accumulator, 16, 16, 16, float>;
using AFrag = wmma::fragment<wmma::matrix_a, 16, 16, 16, __half, wmma::row_major>;
using BFrag = wmma::fragment<wmma::matrix_b, 16, 16, 16, __half, wmma::col_major>;

// ---------------------------------------------------------------------------
// LayerNorm -> fp16 g_xnorm
// ---------------------------------------------------------------------------
__global__ void __launch_bounds__(256) ln_kernel(const float* __restrict__ x,
                                                 const float* __restrict__ w,
                                                 const float* __restrict__ b) {
    int row = blockIdx.x;
    int tid = threadIdx.x;
    const float4* xr = reinterpret_cast<const float4*>(x + (size_t)row * Ee);

    float4 v[4];
    float sum = 0.f, ssq = 0.f;
#pragma unroll
    for (int j = 0; j < 4; j++) {
        v[j] = xr[tid + j * 256];
        sum += v[j].x + v[j].y + v[j].z + v[j].w;
        ssq += v[j].x * v[j].x + v[j].y * v[j].y + v[j].z * v[j].z + v[j].w * v[j].w;
    }
    __shared__ float s_sum[8], s_ssq[8];
#pragma unroll
    for (int o = 16; o; o >>= 1) {
        sum += __shfl_xor_sync(~0u, sum, o);
        ssq += __shfl_xor_sync(~0u, ssq, o);
    }
    if ((tid & 31) == 0) { s_sum[tid >> 5] = sum; s_ssq[tid >> 5] = ssq; }
    __syncthreads();
    if (tid < 32) {
        float ts = (tid < 8) ? s_sum[tid] : 0.f;
        float tq = (tid < 8) ? s_ssq[tid] : 0.f;
#pragma unroll
        for (int o = 4; o; o >>= 1) {
            ts += __shfl_xor_sync(~0u, ts, o);
            tq += __shfl_xor_sync(~0u, tq, o);
        }
        if (tid == 0) { s_sum[0] = ts; s_ssq[0] = tq; }
    }
    __syncthreads();
    float mean = s_sum[0] * (1.0f / Ee);
    float var = s_ssq[0] * (1.0f / Ee) - mean * mean;
    float rstd = rsqrtf(var + 1e-5f);

    const float4* wr = reinterpret_cast<const float4*>(w);
    const float4* br = reinterpret_cast<const float4*>(b);
    __half2* outr = reinterpret_cast<__half2*>(g_xnorm + (size_t)row * Ee);
#pragma unroll
    for (int j = 0; j < 4; j++) {
        int c = tid + j * 256;
        float4 wv = wr[c], bv = br[c];
        float o0 = (v[j].x - mean) * rstd * wv.x + bv.x;
        float o1 = (v[j].y - mean) * rstd * wv.y + bv.y;
        float o2 = (v[j].z - mean) * rstd * wv.z + bv.z;
        float o3 = (v[j].w - mean) * rstd * wv.w + bv.w;
        outr[c * 2]     = __floats2half2_rn(o0, o1);
        outr[c * 2 + 1] = __floats2half2_rn(o2, o3);
    }
}

// ---------------------------------------------------------------------------
// Weight conversion fp32 -> fp16
// ---------------------------------------------------------------------------
__global__ void __launch_bounds__(256) wconv_kernel(const float* __restrict__ wq,
                                                    const float* __restrict__ wk) {
    const float* src = blockIdx.y ? wk : wq;
    __half* dst = blockIdx.y ? g_wk : g_wq;
    size_t i = ((size_t)blockIdx.x * 256 + threadIdx.x) * 4;
    float4 v = *reinterpret_cast<const float4*>(src + i);
    __half2* d2 = reinterpret_cast<__half2*>(dst + i);
    d2[0] = __floats2half2_rn(v.x, v.y);
    d2[1] = __floats2half2_rn(v.z, v.w);
}

// ---------------------------------------------------------------------------
// Pipelined fp16 wmma GEMM (NT), CTA 128x128, 8 warps, warp tile 64x32
// ONE __syncthreads per chunk: WAIT1 -> barrier -> issue load(k+2) -> compute.
// Safe with NSTAGE=3: the barrier at iter k proves every reader finished
// buf (k-1)%3 (read during iter k-1), which is exactly the buffer written
// by the iter-k load of chunk k+2. One group committed per iter (empty on
// skip iters) keeps wait_group 1 <=> "chunk k resident" exact at every k.
// ---------------------------------------------------------------------------
__device__ __forceinline__ void load_chunk(uint32_t sb, const char* Ab, const char* Bbp,
                                           size_t ldab, int kc, int buf, int tid) {
    uint32_t stA = sb + buf * STAGE_BYTES;
    uint32_t stB = stA + STAGE_A_BYTES;
    const char* Ap = Ab + (size_t)kc * (BK * 2);
    const char* Bp = Bbp + (size_t)kc * (BK * 2);
#pragma unroll
    for (int l = 0; l < 4; l++) {
        int idx = tid + l * NTHREADS;    // 0..1023
        int r = idx >> 3, cb = (idx & 7) << 4;
        cp16(stA + r * (ASTR * 2) + cb, Ap + (size_t)r * ldab + cb);
        cp16(stB + r * (ASTR * 2) + cb, Bp + (size_t)r * ldab + cb);
    }
}

template <int NCHUNK>
__device__ __forceinline__ void gemm_pipe(const char* Ab, const char* Bbp, size_t ldab,
                                          char* smem, AccFrag acc[4][2]) {
    uint32_t sb = smem_u32(smem);
    int tid = threadIdx.x;
    int warp = tid >> 5;
    int wm = warp & 1;        // 2 along M, 64 rows each
    int wn = warp >> 1;       // 4 along N, 32 cols each

    load_chunk(sb, Ab, Bbp, ldab, 0, 0, tid);
    CP_COMMIT();
    if (NCHUNK > 1) load_chunk(sb, Ab, Bbp, ldab, 1, 1, tid);
    CP_COMMIT();

    for (int k = 0; k < NCHUNK; k++) {
        CP_WAIT1();               // chunk k resident for this thread
        __syncthreads();          // ...for all threads; buf (k-1)%3 fully consumed
        if (k + 2 < NCHUNK)
            load_chunk(sb, Ab, Bbp, ldab, k + 2, (k + 2) % NSTAGE, tid);
        CP_COMMIT();              // exactly one group per iter (may be empty)

        __half* As = reinterpret_cast<__half*>(smem + (k % NSTAGE) * STAGE_BYTES);
        __half* Bs = As + BM * ASTR;
#pragma unroll
        for (int kk = 0; kk < BK; kk += 16) {
            AFrag af[4];
            BFrag bf[2];
#pragma unroll
            for (int i = 0; i < 4; i++)
                wmma::load_matrix_sync(af[i], As + (wm * 64 + i * 16) * ASTR + kk, ASTR);
#pragma unroll
            for (int j = 0; j < 2; j++)
                wmma::load_matrix_sync(bf[j], Bs + (wn * 32 + j * 16) * ASTR + kk, ASTR);
#pragma unroll
            for (int i = 0; i < 4; i++)
#pragma unroll
                for (int j = 0; j < 2; j++)
                    wmma::mma_sync(acc[i][j], af[i], bf[j], acc[i][j]);
        }
    }
    __syncthreads();   // final: all reads done before smem reused for Cs
}

__device__ __forceinline__ void store_acc(float* Cs, AccFrag acc[4][2]) {
    int warp = threadIdx.x >> 5;
    int wm = warp & 1, wn = warp >> 1;
#pragma unroll
    for (int i = 0; i < 4; i++)
#pragma unroll
        for (int j = 0; j < 2; j++)
            wmma::store_matrix_sync(Cs + (wm * 64 + i * 16) * CSTR + wn * 32 + j * 16,
                                    acc[i][j], CSTR, wmma::mem_row_major);
}

// ---------------------------------------------------------------------------
// Projection GEMM + bias + RoPE; fp32 q/k to d_out (streaming), fp16 copies
// ---------------------------------------------------------------------------
__global__ void __launch_bounds__(NTHREADS, 2) proj_cp_kernel(
    const float* __restrict__ bq, const float* __restrict__ bk,
    const float* __restrict__ embed, const int* __restrict__ posids,
    float* __restrict__ qout, float* __restrict__ kout)
{
    extern __shared__ __align__(128) char smem[];
    int z = blockIdx.z;
    const __half* W   = z ? g_wk : g_wq;
    const float* bias = z ? bk : bq;
    float* outp       = z ? kout : qout;
    __half* routp     = z ? g_kr : g_qr;
    const int m0 = blockIdx.x * BM;   // x fastest: consecutive CTAs share the weight panel
    const int n0 = blockIdx.y * BN;

    AccFrag acc[4][2];
#pragma unroll
    for (int i = 0; i < 4; i++)
#pragma unroll
        for (int j = 0; j < 2; j++)
            wmma::fill_fragment(acc[i][j], 0.f);

    gemm_pipe<Ee / BK>(reinterpret_cast<const char*>(g_xnorm + (size_t)m0 * Ee),
                       reinterpret_cast<const char*>(W + (size_t)n0 * Ee),
                       (size_t)Ee * 2, smem, acc);

    float* Cs = reinterpret_cast<float*>(smem);
    store_acc(Cs, acc);
    __syncthreads();

    int tid = threadIdx.x;
#pragma unroll 4
    for (int i = 0; i < 32; i++) {
        int it = tid + i * NTHREADS;     // 0..8191 over 128x64 pairs
        int r = it >> 6;                 // 0..127
        int pc = it & 63;
        int c = pc << 1;
        int m = m0 + r, f = n0 + c;
        float v0 = Cs[r * CSTR + c] + bias[f];
        float v1 = Cs[r * CSTR + c + 1] + bias[f + 1];
        int d = f & 255;
        if (d < Rr) {
            int pos = posids[m];
            int i2 = d >> 1;
            float sn = embed[pos * Rr + i2];
            float co = embed[pos * Rr + 32 + i2];
            float o0 = v0 * co - v1 * sn;
            float o1 = v1 * co + v0 * sn;
            v0 = o0; v1 = o1;
        }
        int b_ = m >> 11, s_ = m & 2047, h_ = f >> 8;
        size_t off = ((size_t)(b_ * Hh + h_) * Ss + s_) * Dd + d;
        stcs2(outp + off, make_float2(v0, v1));   // streaming: never re-read
        *reinterpret_cast<__half2*>(routp + off) = __floats2half2_rn(v0, v1);
    }
}

// ---------------------------------------------------------------------------
// Scores GEMM: scores = Qh.Kh^T / 16, causal tile skip
// ---------------------------------------------------------------------------
__global__ void __launch_bounds__(NTHREADS, 2) scores_cp_kernel(float* __restrict__ attn)
{
    int kt = blockIdx.x, qt = blockIdx.y, bh = blockIdx.z;
    if (kt > qt) return;

    extern __shared__ __align__(128) char smem[];
    int m0 = qt * BM, n0 = kt * BN;
    const __half* Q = g_qr + (size_t)bh * Ss * Dd;
    const __half* Kv = g_kr + (size_t)bh * Ss * Dd;

    AccFrag acc[4][2];
#pragma unroll
    for (int i = 0; i < 4; i++)
#pragma unroll
        for (int j = 0; j < 2; j++)
            wmma::fill_fragment(acc[i][j], 0.f);

    gemm_pipe<Dd / BK>(reinterpret_cast<const char*>(Q + (size_t)m0 * Dd),
                       reinterpret_cast<const char*>(Kv + (size_t)n0 * Dd),
                       (size_t)Dd * 2, smem, acc);

    float* Cs = reinterpret_cast<float*>(smem);
    store_acc(Cs, acc);
    __syncthreads();

    float* out_base = attn + (size_t)bh * Ss * Ss;
#pragma unroll
    for (int i = 0; i < 16; i++) {
        int it = threadIdx.x + i * NTHREADS;   // 0..4095 float4s over 128x128
        int r = it >> 5;
        int c4 = (it & 31) << 2;
        float4 v = *reinterpret_cast<const float4*>(Cs + r * CSTR + c4);
        v.x *= 0.0625f; v.y *= 0.0625f; v.z *= 0.0625f; v.w *= 0.0625f;
        stcs4(out_base + (size_t)(m0 + r) * Ss + n0 + c4, v);   // streaming
    }
}

// ---------------------------------------------------------------------------
// In-place masked softmax, float4 vectorized; final writes streaming
// ---------------------------------------------------------------------------
__global__ void __launch_bounds__(256) softmax_kernel(float* __restrict__ attn) {
    int row = blockIdx.x;
    int q = row & 2047;
    int nv = q + 1;
    float* rowp = attn + (size_t)row * Ss;
    int tid = threadIdx.x;

    float4 vals[2];
    float mx = -INFINITY;
#pragma unroll
    for (int j = 0; j < 2; j++) {
        int k4 = (tid + j * 256) << 2;
        float4 v;
        if (k4 + 3 < nv) {
            v = *reinterpret_cast<const float4*>(rowp + k4);
        } else {
            v.x = (k4 + 0 < nv) ? rowp[k4 + 0] : -INFINITY;
            v.y = (k4 + 1 < nv) ? rowp[k4 + 1] : -INFINITY;
            v.z = (k4 + 2 < nv) ? rowp[k4 + 2] : -INFINITY;
            v.w = (k4 + 3 < nv) ? rowp[k4 + 3] : -INFINITY;
        }
        vals[j] = v;
        mx = fmaxf(mx, fmaxf(fmaxf(v.x, v.y), fmaxf(v.z, v.w)));
    }
    __shared__ float sh[8];
#pragma unroll
    for (int o = 16; o; o >>= 1) mx = fmaxf(mx, __shfl_xor_sync(~0u, mx, o));
    if ((tid & 31) == 0) sh[tid >> 5] = mx;
    __syncthreads();
    if (tid < 32) {
        float t = (tid < 8) ? sh[tid] : -INFINITY;
#pragma unroll
        for (int o = 4; o; o >>= 1) t = fmaxf(t, __shfl_xor_sync(~0u, t, o));
        if (tid == 0) sh[0] = t;
    }
    __syncthreads();
    float M = sh[0];
    __syncthreads();

    float sum = 0.f;
#pragma unroll
    for (int j = 0; j < 2; j++) {
        float4 v = vals[j];
        v.x = (v.x == -INFINITY) ? 0.f : __expf(v.x - M);
        v.y = (v.y == -INFINITY) ? 0.f : __expf(v.y - M);
        v.z = (v.z == -INFINITY) ? 0.f : __expf(v.z - M);
        v.w = (v.w == -INFINITY) ? 0.f : __expf(v.w - M);
        vals[j] = v;
        sum += v.x + v.y + v.z + v.w;
    }
#pragma unroll
    for (int o = 16; o; o >>= 1) sum += __shfl_xor_sync(~0u, sum, o);
    if ((tid & 31) == 0) sh[tid >> 5] = sum;
    __syncthreads();
    if (tid < 32) {
        float t = (tid < 8) ? sh[tid] : 0.f;
#pragma unroll
        for (int o = 4; o; o >>= 1) t += __shfl_xor_sync(~0u, t, o);
        if (tid == 0) sh[0] = t;
    }
    __syncthreads();
    float inv = 1.0f / sh[0];
#pragma unroll
    for (int j = 0; j < 2; j++) {
        int k4 = (tid + j * 256) << 2;
        float4 v = vals[j];
        v.x *= inv; v.y *= inv; v.z *= inv; v.w *= inv;
        stcs4(rowp + k4, v);            // streaming: never re-read
    }
}

// ---------------------------------------------------------------------------
extern "C" void kernel_launch(void* const* d_in, const int* in_sizes, int n_in,
                              void* d_out, int out_size) {
    const float* x     = (const float*)d_in[0];
    const float* q_w   = (const float*)d_in[1];
    const float* q_b   = (const float*)d_in[2];
    const float* k_w   = (const float*)d_in[3];
    const float* k_b   = (const float*)d_in[4];
    const float* ln_w  = (const float*)d_in[5];
    const float* ln_b  = (const float*)d_in[6];
    const float* embed = (const float*)d_in[7];
    const int*   pos   = (const int*)d_in[8];

    float* out   = (float*)d_out;
    float* q_out = out;
    float* k_out = out + QK_ELEMS;
    float* attn  = out + 2 * QK_ELEMS;

    cudaFuncSetAttribute(proj_cp_kernel, cudaFuncAttributeMaxDynamicSharedMemorySize, (int)GEMM_SMEM);
    cudaFuncSetAttribute(scores_cp_kernel, cudaFuncAttributeMaxDynamicSharedMemorySize, (int)GEMM_SMEM);

    ln_kernel<<<Mtot, 256>>>(x, ln_w, ln_b);

    dim3 gw((unsigned)(((size_t)Ee * Ee) / 1024), 2);   // 16384 x 2
    wconv_kernel<<<gw, 256>>>(q_w, k_w);

    dim3 gp(Mtot / BM, Ee / BN, 2);          // (32, 32, 2), x over M
    proj_cp_kernel<<<gp, NTHREADS, GEMM_SMEM>>>(q_b, k_b, embed, pos, q_out, k_out);

    dim3 g2(Ss / BN, Ss / BM, Bb * Hh);      // (16, 16, 32)
    scores_cp_kernel<<<g2, NTHREADS, GEMM_SMEM>>>(attn);

    softmax_kernel<<<Bb * Hh * Ss, 256>>>(attn);
}